// round 12
// baseline (speedup 1.0000x reference)
#include <cuda_runtime.h>
#include <cuda_bf16.h>
#include <stdint.h>

#define MAXN 100000
#define MAXE 1600000
#define MAXEL 200000

// ---------------- static scratch (A+B = 102MB, fits 126MB L2) ----------------
__device__ float g_bufA[(size_t)MAXN * 128];
__device__ float g_bufB[(size_t)MAXN * 128];
__device__ float g_dinv[MAXN];
__device__ int   g_cnt[MAXN];
__device__ int   g_cur[MAXN];
__device__ int   g_rowptr[MAXN + 1];
__device__ int   g_bsum[512];
__device__ int   g_boff[512];
__device__ int   g_esrc[MAXE];
__device__ int   g_is64;
// per-layer pre-split weights, swizzled ldmatrix layout (row stride 256B,
// 16B-chunk c at (c ^ (row&7))).  slots: {hi,lo} x 3 layers
__device__ __nv_bfloat16 g_w[6 * 128 * 128];

// ---------------- helpers ----------------
__device__ __forceinline__ uint32_t smem_u32(const void* p) {
    uint32_t a;
    asm("{ .reg .u64 t; cvta.to.shared.u64 t, %1; cvt.u32.u64 %0, t; }" : "=r"(a) : "l"(p));
    return a;
}
__device__ __forceinline__ uint32_t pack2(float a, float b) {
    __nv_bfloat162 t = __floats2bfloat162_rn(a, b);
    return *reinterpret_cast<uint32_t*>(&t);
}
__device__ __forceinline__ void relu4(float4& v) {
    v.x = fmaxf(v.x, 0.f); v.y = fmaxf(v.y, 0.f);
    v.z = fmaxf(v.z, 0.f); v.w = fmaxf(v.w, 0.f);
}
__device__ __forceinline__ void ldsm_x4(uint32_t* r, uint32_t addr) {
    asm volatile("ldmatrix.sync.aligned.m8n8.x4.shared.b16 {%0,%1,%2,%3}, [%4];"
                 : "=r"(r[0]), "=r"(r[1]), "=r"(r[2]), "=r"(r[3]) : "r"(addr));
}
__device__ __forceinline__ void mma_bf16(float* d, const uint32_t* a, const uint32_t* b) {
    asm volatile(
        "mma.sync.aligned.m16n8k16.row.col.f32.bf16.bf16.f32 "
        "{%0,%1,%2,%3}, {%4,%5,%6,%7}, {%8,%9}, {%0,%1,%2,%3};"
        : "+f"(d[0]), "+f"(d[1]), "+f"(d[2]), "+f"(d[3])
        : "r"(a[0]), "r"(a[1]), "r"(a[2]), "r"(a[3]), "r"(b[0]), "r"(b[1]));
}
__device__ __forceinline__ int eidx(const void* p, size_t i, int is64) {
    return is64 ? (int)((const long long*)p)[i] : ((const int*)p)[i];
}

// ---------------- preproc ----------------
__global__ void init_k(const void* ei, int n) {
    int i = blockIdx.x * blockDim.x + threadIdx.x;
    if (i < n) g_cnt[i] = 0;
    if (blockIdx.x == 0) {
        __shared__ int ok;
        if (threadIdx.x == 0) ok = 1;
        __syncthreads();
        const long long* p = (const long long*)ei;
        for (int j = threadIdx.x; j < 1024; j += blockDim.x) {
            long long v = p[j];
            if (v < 0 || v >= (long long)n) ok = 0;
        }
        __syncthreads();
        if (threadIdx.x == 0) g_is64 = ok;
    }
}
__global__ void count_k(const void* ei, int E) {
    int e = blockIdx.x * blockDim.x + threadIdx.x;
    if (e >= E) return;
    atomicAdd(&g_cnt[eidx(ei, (size_t)E + e, g_is64)], 1);
}
__global__ void scan1_k(int n) {
    __shared__ int s[512];
    int t = threadIdx.x, idx = blockIdx.x * 512 + t;
    int v = (idx < n) ? g_cnt[idx] : 0;
    s[t] = v;
    __syncthreads();
    #pragma unroll
    for (int off = 1; off < 512; off <<= 1) {
        int add = (t >= off) ? s[t - off] : 0;
        __syncthreads();
        s[t] += add;
        __syncthreads();
    }
    if (idx < n) g_rowptr[idx] = s[t] - v;
    if (t == 511) g_bsum[blockIdx.x] = s[511];
}
__global__ void scan2_k(int nb) {
    __shared__ int s[512];
    int t = threadIdx.x;
    int v = (t < nb) ? g_bsum[t] : 0;
    s[t] = v;
    __syncthreads();
    #pragma unroll
    for (int off = 1; off < 512; off <<= 1) {
        int add = (t >= off) ? s[t - off] : 0;
        __syncthreads();
        s[t] += add;
        __syncthreads();
    }
    g_boff[t] = s[t] - v;
}
__global__ void scan3_k(int n, int E) {
    int idx = blockIdx.x * 512 + threadIdx.x;
    if (idx < n) {
        int v = g_rowptr[idx] + g_boff[blockIdx.x];
        g_rowptr[idx] = v;
        g_cur[idx] = v;
        g_dinv[idx] = rsqrtf((float)g_cnt[idx] + 1.0f);
    }
    if (idx == 0) g_rowptr[n] = E;
}
__global__ void fill_k(const void* ei, int E) {
    int e = blockIdx.x * blockDim.x + threadIdx.x;
    if (e >= E) return;
    int is64 = g_is64;
    int src = eidx(ei, (size_t)e, is64);
    int dst = eidx(ei, (size_t)E + e, is64);
    g_esrc[atomicAdd(&g_cur[dst], 1)] = src;
}

// ---------------- W split ----------------
template<int TN>
__global__ void wsplit_k(const float* __restrict__ W, __nv_bfloat16* __restrict__ whi,
                         __nv_bfloat16* __restrict__ wlo) {
    int idx = blockIdx.x * blockDim.x + threadIdx.x;
    if (idx >= 128 * TN) return;
    int k = idx / TN, nn = idx - k * TN;
    float v = W[idx];
    __nv_bfloat16 hi = __float2bfloat16_rn(v);
    __nv_bfloat16 lo = __float2bfloat16_rn(v - __bfloat162float(hi));
    int c = k >> 3;
    int off = nn * 256 + (((c ^ (nn & 7)) << 4) | ((k & 7) << 1));
    *(__nv_bfloat16*)((char*)whi + off) = hi;
    *(__nv_bfloat16*)((char*)wlo + off) = lo;
}

// ---------------- mma.sync GEMM (rows [r0, n), output row stride OSTR) ------
// In-place capable: X tile fully read into smem (+syncthreads) before epilogue.
template<int TN, bool RELU, bool SCALE, int OSTR>
__global__ void __launch_bounds__(256)
gemm_mma_k(const float* __restrict__ X, float* __restrict__ out, int r0, int n,
           const __nv_bfloat16* __restrict__ gwhi, const __nv_bfloat16* __restrict__ gwlo) {
    extern __shared__ char sm[];
    constexpr int NT = TN / 16;
    char* xhi = sm;
    char* xlo = sm + 32768;
    char* whi = sm + 65536;
    char* wlo = whi + TN * 256;

    int tid = threadIdx.x;
    int m0 = r0 + blockIdx.x * 128;

    {
        const uint4* gh = (const uint4*)gwhi;
        const uint4* gl = (const uint4*)gwlo;
        uint4* dh = (uint4*)whi;
        uint4* dl = (uint4*)wlo;
        #pragma unroll 4
        for (int i = tid; i < TN * 16; i += 256) { dh[i] = gh[i]; dl[i] = gl[i]; }
    }
    {
        int r = tid >> 1, h = tid & 1;
        int row = m0 + r;
        bool ok = row < n;
        const float4* xr = (const float4*)(X + (size_t)row * 128) + h * 16;
        const float4 z4 = make_float4(0.f, 0.f, 0.f, 0.f);
        #pragma unroll
        for (int j = 0; j < 8; j++) {
            float4 v0 = ok ? xr[j * 2] : z4;
            float4 v1 = ok ? xr[j * 2 + 1] : z4;
            if (RELU) { relu4(v0); relu4(v1); }
            uint4 hv, lv;
            hv.x = pack2(v0.x, v0.y); hv.y = pack2(v0.z, v0.w);
            hv.z = pack2(v1.x, v1.y); hv.w = pack2(v1.z, v1.w);
            __nv_bfloat162 h0 = *(__nv_bfloat162*)&hv.x;
            __nv_bfloat162 h1 = *(__nv_bfloat162*)&hv.y;
            __nv_bfloat162 h2 = *(__nv_bfloat162*)&hv.z;
            __nv_bfloat162 h3 = *(__nv_bfloat162*)&hv.w;
            lv.x = pack2(v0.x - __low2float(h0), v0.y - __high2float(h0));
            lv.y = pack2(v0.z - __low2float(h1), v0.w - __high2float(h1));
            lv.z = pack2(v1.x - __low2float(h2), v1.y - __high2float(h2));
            lv.w = pack2(v1.z - __low2float(h3), v1.w - __high2float(h3));
            int c = h * 8 + j;
            int off = r * 256 + ((c ^ (r & 7)) << 4);
            *(uint4*)(xhi + off) = hv;
            *(uint4*)(xlo + off) = lv;
        }
    }
    __syncthreads();

    int wrp = tid >> 5, lane = tid & 31;
    int wm = wrp & 3;
    int wnb = (wrp >> 2) * (TN / 2);
    uint32_t xhi_u = smem_u32(xhi), xlo_u = smem_u32(xlo);
    uint32_t whi_u = smem_u32(whi), wlo_u = smem_u32(wlo);
    int a_row_in = ((lane >> 3) & 1) * 8 + (lane & 7);
    int a_kc = lane >> 4;
    int b_row_in = ((lane >> 4) << 3) + (lane & 7);
    int b_kc = (lane >> 3) & 1;

    float acc[2][NT][4];
    #pragma unroll
    for (int i = 0; i < 2; i++)
        #pragma unroll
        for (int j = 0; j < NT; j++)
            #pragma unroll
            for (int q = 0; q < 4; q++) acc[i][j][q] = 0.f;

    #pragma unroll
    for (int k = 0; k < 8; k++) {
        int c0 = k * 2;
        uint32_t ahi[2][4], alo[2][4];
        #pragma unroll
        for (int mt = 0; mt < 2; mt++) {
            int rr = wm * 32 + mt * 16 + a_row_in;
            int cc = c0 + a_kc;
            uint32_t off = rr * 256 + (((cc ^ (rr & 7)) & 15) << 4);
            ldsm_x4(ahi[mt], xhi_u + off);
            ldsm_x4(alo[mt], xlo_u + off);
        }
        uint32_t bhi[NT][2], blo[NT][2];
        #pragma unroll
        for (int nt = 0; nt < NT; nt += 2) {
            int rr = wnb + nt * 8 + b_row_in;
            int cc = c0 + b_kc;
            uint32_t off = rr * 256 + (((cc ^ (rr & 7)) & 15) << 4);
            uint32_t t[4];
            ldsm_x4(t, whi_u + off);
            bhi[nt][0] = t[0]; bhi[nt][1] = t[1];
            bhi[nt + 1][0] = t[2]; bhi[nt + 1][1] = t[3];
            ldsm_x4(t, wlo_u + off);
            blo[nt][0] = t[0]; blo[nt][1] = t[1];
            blo[nt + 1][0] = t[2]; blo[nt + 1][1] = t[3];
        }
        #pragma unroll
        for (int mt = 0; mt < 2; mt++)
            #pragma unroll
            for (int nt = 0; nt < NT; nt++) {
                mma_bf16(acc[mt][nt], ahi[mt], bhi[nt]);
                mma_bf16(acc[mt][nt], ahi[mt], blo[nt]);
                mma_bf16(acc[mt][nt], alo[mt], bhi[nt]);
            }
    }

    #pragma unroll
    for (int mt = 0; mt < 2; mt++) {
        int row0 = m0 + wm * 32 + mt * 16 + (lane >> 2);
        int row1 = row0 + 8;
        float dv0 = 1.f, dv1 = 1.f;
        if (SCALE) {
            dv0 = (row0 < n) ? g_dinv[row0] : 0.f;
            dv1 = (row1 < n) ? g_dinv[row1] : 0.f;
        }
        #pragma unroll
        for (int nt = 0; nt < NT; nt++) {
            int col = wnb + nt * 8 + (lane & 3) * 2;
            if (row0 < n)
                *(float2*)(out + (size_t)row0 * OSTR + col) =
                    make_float2(acc[mt][nt][0] * dv0, acc[mt][nt][1] * dv0);
            if (row1 < n)
                *(float2*)(out + (size_t)row1 * OSTR + col) =
                    make_float2(acc[mt][nt][2] * dv1, acc[mt][nt][3] * dv1);
        }
    }
}

// ---------------- pull aggregation (nodes [n0,n1), input row stride ISTRF floats) --
template<int D, bool SRCSCALE, int ISTRF>
__global__ void agg_k(const float* __restrict__ tmp, const float* __restrict__ bias,
                      float* __restrict__ out, int n0, int n1) {
    int w = n0 + ((blockIdx.x * blockDim.x + threadIdx.x) >> 5);
    if (w >= n1) return;
    int l = threadIdx.x & 31;
    int s0 = g_rowptr[w], s1 = g_rowptr[w + 1];
    float dv = g_dinv[w];
    if (D == 128) {
        const float4* t = (const float4*)tmp;
        float4 sv = t[(size_t)w * (ISTRF / 4) + l];
        float4 acc;
        if (SRCSCALE) {
            acc.x = sv.x * dv; acc.y = sv.y * dv; acc.z = sv.z * dv; acc.w = sv.w * dv;
        } else acc = sv;
        for (int j = s0; j < s1; j++) {
            int s = g_esrc[j];
            float4 v = t[(size_t)s * (ISTRF / 4) + l];
            if (SRCSCALE) {
                float ds = g_dinv[s];
                acc.x = fmaf(v.x, ds, acc.x); acc.y = fmaf(v.y, ds, acc.y);
                acc.z = fmaf(v.z, ds, acc.z); acc.w = fmaf(v.w, ds, acc.w);
            } else {
                acc.x += v.x; acc.y += v.y; acc.z += v.z; acc.w += v.w;
            }
        }
        float4 bb = ((const float4*)bias)[l];
        float4 o;
        o.x = fmaf(acc.x, dv, bb.x); o.y = fmaf(acc.y, dv, bb.y);
        o.z = fmaf(acc.z, dv, bb.z); o.w = fmaf(acc.w, dv, bb.w);
        ((float4*)out)[(size_t)w * 32 + l] = o;
    } else {
        const float2* t = (const float2*)tmp;
        float2 acc = t[(size_t)w * (ISTRF / 2) + l];
        for (int j = s0; j < s1; j++) {
            float2 v = t[(size_t)g_esrc[j] * (ISTRF / 2) + l];
            acc.x += v.x; acc.y += v.y;
        }
        float2 bb = ((const float2*)bias)[l];
        ((float2*)out)[(size_t)w * 32 + l] =
            make_float2(fmaf(acc.x, dv, bb.x), fmaf(acc.y, dv, bb.y));
    }
}

// ---------------- decode: 2 pairs per warp, float4 loads ----------------
__global__ void decode_k(const float* __restrict__ z, const void* eli,
                         float* __restrict__ out, int EL) {
    int gid = blockIdx.x * blockDim.x + threadIdx.x;
    int lane = threadIdx.x & 31;
    int p = (gid >> 5) * 2 + (lane >> 4);
    if (p >= EL) return;
    int l = lane & 15;
    int is64 = g_is64;
    int a = eidx(eli, (size_t)p, is64);
    int b = eidx(eli, (size_t)EL + p, is64);
    const float4* z4 = (const float4*)z;
    float4 va = z4[(size_t)a * 16 + l];
    float4 vb = z4[(size_t)b * 16 + l];
    float s = va.x * vb.x + va.y * vb.y + va.z * vb.z + va.w * vb.w;
    #pragma unroll
    for (int off = 8; off > 0; off >>= 1)
        s += __shfl_xor_sync(0xffffffffu, s, off);
    if (l == 0) out[p] = s;
}

// ---------------- launch ----------------
extern "C" void kernel_launch(void* const* d_in, const int* in_sizes, int n_in,
                              void* d_out, int out_size) {
    const float* x  = (const float*)d_in[0];
    const void*  ei = d_in[1];
    const void*  eli= d_in[2];
    const float* W1 = (const float*)d_in[3];
    const float* b1 = (const float*)d_in[4];
    const float* W2 = (const float*)d_in[5];
    const float* b2 = (const float*)d_in[6];
    const float* W3 = (const float*)d_in[7];
    const float* b3 = (const float*)d_in[8];
    float* out = (float*)d_out;

    int N  = in_sizes[0] / 128;
    int E  = in_sizes[1] / 2;
    int EL = in_sizes[2] / 2;

    float *A, *B;
    cudaGetSymbolAddress((void**)&A, g_bufA);
    cudaGetSymbolAddress((void**)&B, g_bufB);
    __nv_bfloat16* wbase;
    cudaGetSymbolAddress((void**)&wbase, g_w);
    __nv_bfloat16* w1h = wbase;             __nv_bfloat16* w1l = wbase + 1 * 16384;
    __nv_bfloat16* w2h = wbase + 2 * 16384; __nv_bfloat16* w2l = wbase + 3 * 16384;
    __nv_bfloat16* w3h = wbase + 4 * 16384; __nv_bfloat16* w3l = wbase + 5 * 16384;

    static cudaStream_t s2 = nullptr;
    static cudaEvent_t evF, evJ, evA1[4], evG2, evA2[4], evG3;
    if (!s2) {
        cudaStreamCreateWithFlags(&s2, cudaStreamNonBlocking);
        cudaEventCreateWithFlags(&evF, cudaEventDisableTiming);
        cudaEventCreateWithFlags(&evJ, cudaEventDisableTiming);
        cudaEventCreateWithFlags(&evG2, cudaEventDisableTiming);
        cudaEventCreateWithFlags(&evG3, cudaEventDisableTiming);
        for (int i = 0; i < 4; i++) {
            cudaEventCreateWithFlags(&evA1[i], cudaEventDisableTiming);
            cudaEventCreateWithFlags(&evA2[i], cudaEventDisableTiming);
        }
    }

    int smem128 = 65536 + 2 * 128 * 256;
    int smem64  = 65536 + 2 * 64 * 256;
    cudaFuncSetAttribute(gemm_mma_k<128, false, false, 128>, cudaFuncAttributeMaxDynamicSharedMemorySize, smem128);
    cudaFuncSetAttribute(gemm_mma_k<128, true,  true, 128>,  cudaFuncAttributeMaxDynamicSharedMemorySize, smem128);
    cudaFuncSetAttribute(gemm_mma_k<64,  true,  true, 128>,  cudaFuncAttributeMaxDynamicSharedMemorySize, smem64);

    int nb = (N + 511) / 512;
    int hc = ((N / 4) + 127) & ~127;
    int cb[5] = {0, hc, 2 * hc, 3 * hc, N};

    // fork: preprocessing on s2
    cudaEventRecord(evF, 0);
    cudaStreamWaitEvent(s2, evF, 0);
    init_k<<<(N + 255) / 256, 256, 0, s2>>>(ei, N);
    count_k<<<(E + 255) / 256, 256, 0, s2>>>(ei, E);
    scan1_k<<<nb, 512, 0, s2>>>(N);
    scan2_k<<<1, 512, 0, s2>>>(nb);
    scan3_k<<<nb, 512, 0, s2>>>(N, E);
    fill_k<<<(E + 255) / 256, 256, 0, s2>>>(ei, E);
    cudaEventRecord(evJ, s2);

    // s0: weight splits + full layer-1 GEMM (overlaps preprocessing)
    wsplit_k<128><<<(128 * 128 + 255) / 256, 256>>>(W1, w1h, w1l);
    wsplit_k<128><<<(128 * 128 + 255) / 256, 256>>>(W2, w2h, w2l);
    wsplit_k<64><<<(128 * 64 + 255) / 256, 256>>>(W3, w3h, w3l);
    gemm_mma_k<128, false, false, 128><<<(N + 127) / 128, 256, smem128>>>(x, A, 0, N, w1h, w1l);

    cudaStreamWaitEvent(0, evJ, 0);

    // boundary 1: agg1 A->B (s0) ; gemm2 B->B in-place (s2), chunk-staggered
    for (int i = 0; i < 4; i++) {
        int n0 = cb[i], n1 = cb[i + 1];
        agg_k<128, true, 128><<<((n1 - n0) * 32 + 255) / 256, 256>>>(A, b1, B, n0, n1);
        cudaEventRecord(evA1[i], 0);
        cudaStreamWaitEvent(s2, evA1[i], 0);
        gemm_mma_k<128, true, true, 128><<<(n1 - n0 + 127) / 128, 256, smem128, s2>>>(
            B, B, n0, n1, w2h, w2l);
    }
    cudaEventRecord(evG2, s2);
    cudaStreamWaitEvent(0, evG2, 0);

    // boundary 2: agg2 B->A (s0) ; gemm3 A->A in-place stride-128 out (s2)
    for (int i = 0; i < 4; i++) {
        int n0 = cb[i], n1 = cb[i + 1];
        agg_k<128, false, 128><<<((n1 - n0) * 32 + 255) / 256, 256>>>(B, b2, A, n0, n1);
        cudaEventRecord(evA2[i], 0);
        cudaStreamWaitEvent(s2, evA2[i], 0);
        gemm_mma_k<64, true, true, 128><<<(n1 - n0 + 127) / 128, 256, smem64, s2>>>(
            A, A, n0, n1, w3h, w3l);
    }
    cudaEventRecord(evG3, s2);
    cudaStreamWaitEvent(0, evG3, 0);

    // final: agg3 A(stride128) -> B dense 64, then decode
    agg_k<64, false, 128><<<(N * 32 + 255) / 256, 256>>>(A, b3, B, 0, N);
    decode_k<<<((EL + 1) / 2 * 32 + 255) / 256, 256>>>(B, eli, out, EL);
}

// round 16
// speedup vs baseline: 1.5610x; 1.5610x over previous
#include <cuda_runtime.h>
#include <cuda_bf16.h>
#include <stdint.h>

#define MAXN 100000
#define MAXE 1600000
#define MAXEL 200000

// ---------------- static scratch ----------------
__device__ float g_bufA[(size_t)MAXN * 128];
__device__ float g_bufB[(size_t)MAXN * 128];
__device__ float g_dinv[MAXN];
__device__ int   g_cnt[MAXN];
__device__ int   g_cur[MAXN];
__device__ int   g_rowptr[MAXN + 1];
__device__ int   g_bsum[512];
__device__ int   g_boff[512];
__device__ int   g_esrc[MAXE];
__device__ int   g_is64;
// per-layer pre-split weights, swizzled ldmatrix layout: [TN rows][128 k] bf16,
// row stride 256B, 16B-chunk c stored at (c ^ (row&7)).  slots: {hi,lo} x 3 layers
__device__ __nv_bfloat16 g_w[6 * 128 * 128];

// ---------------- helpers ----------------
__device__ __forceinline__ uint32_t smem_u32(const void* p) {
    uint32_t a;
    asm("{ .reg .u64 t; cvta.to.shared.u64 t, %1; cvt.u32.u64 %0, t; }" : "=r"(a) : "l"(p));
    return a;
}
__device__ __forceinline__ uint32_t pack2(float a, float b) {
    __nv_bfloat162 t = __floats2bfloat162_rn(a, b);
    return *reinterpret_cast<uint32_t*>(&t);
}
__device__ __forceinline__ void relu4(float4& v) {
    v.x = fmaxf(v.x, 0.f); v.y = fmaxf(v.y, 0.f);
    v.z = fmaxf(v.z, 0.f); v.w = fmaxf(v.w, 0.f);
}
__device__ __forceinline__ void ldsm_x4(uint32_t* r, uint32_t addr) {
    asm volatile("ldmatrix.sync.aligned.m8n8.x4.shared.b16 {%0,%1,%2,%3}, [%4];"
                 : "=r"(r[0]), "=r"(r[1]), "=r"(r[2]), "=r"(r[3]) : "r"(addr));
}
__device__ __forceinline__ void mma_bf16(float* d, const uint32_t* a, const uint32_t* b) {
    asm volatile(
        "mma.sync.aligned.m16n8k16.row.col.f32.bf16.bf16.f32 "
        "{%0,%1,%2,%3}, {%4,%5,%6,%7}, {%8,%9}, {%0,%1,%2,%3};"
        : "+f"(d[0]), "+f"(d[1]), "+f"(d[2]), "+f"(d[3])
        : "r"(a[0]), "r"(a[1]), "r"(a[2]), "r"(a[3]), "r"(b[0]), "r"(b[1]));
}
__device__ __forceinline__ int eidx(const void* p, size_t i, int is64) {
    return is64 ? (int)((const long long*)p)[i] : ((const int*)p)[i];
}

// ---------------- preproc ----------------
__global__ void init_k(const void* ei, int n) {
    int i = blockIdx.x * blockDim.x + threadIdx.x;
    if (i < n) g_cnt[i] = 0;
    if (blockIdx.x == 0) {
        __shared__ int ok;
        if (threadIdx.x == 0) ok = 1;
        __syncthreads();
        const long long* p = (const long long*)ei;
        for (int j = threadIdx.x; j < 1024; j += blockDim.x) {
            long long v = p[j];
            if (v < 0 || v >= (long long)n) ok = 0;
        }
        __syncthreads();
        if (threadIdx.x == 0) g_is64 = ok;
    }
}
__global__ void count_k(const void* ei, int E) {
    int e = blockIdx.x * blockDim.x + threadIdx.x;
    if (e >= E) return;
    atomicAdd(&g_cnt[eidx(ei, (size_t)E + e, g_is64)], 1);
}
__global__ void scan1_k(int n) {
    __shared__ int s[512];
    int t = threadIdx.x, idx = blockIdx.x * 512 + t;
    int v = (idx < n) ? g_cnt[idx] : 0;
    s[t] = v;
    __syncthreads();
    #pragma unroll
    for (int off = 1; off < 512; off <<= 1) {
        int add = (t >= off) ? s[t - off] : 0;
        __syncthreads();
        s[t] += add;
        __syncthreads();
    }
    if (idx < n) g_rowptr[idx] = s[t] - v;
    if (t == 511) g_bsum[blockIdx.x] = s[511];
}
__global__ void scan2_k(int nb) {
    __shared__ int s[512];
    int t = threadIdx.x;
    int v = (t < nb) ? g_bsum[t] : 0;
    s[t] = v;
    __syncthreads();
    #pragma unroll
    for (int off = 1; off < 512; off <<= 1) {
        int add = (t >= off) ? s[t - off] : 0;
        __syncthreads();
        s[t] += add;
        __syncthreads();
    }
    g_boff[t] = s[t] - v;
}
__global__ void scan3_k(int n, int E) {   // + dinv + fill cursor
    int idx = blockIdx.x * 512 + threadIdx.x;
    if (idx < n) {
        int v = g_rowptr[idx] + g_boff[blockIdx.x];
        g_rowptr[idx] = v;
        g_cur[idx] = v;
        g_dinv[idx] = rsqrtf((float)g_cnt[idx] + 1.0f);
    }
    if (idx == 0) g_rowptr[n] = E;
}
__global__ void fill_k(const void* ei, int E) {
    int e = blockIdx.x * blockDim.x + threadIdx.x;
    if (e >= E) return;
    int is64 = g_is64;
    int src = eidx(ei, (size_t)e, is64);
    int dst = eidx(ei, (size_t)E + e, is64);
    g_esrc[atomicAdd(&g_cur[dst], 1)] = src;
}

// ---------------- W split ----------------
template<int TN>
__global__ void wsplit_k(const float* __restrict__ W, __nv_bfloat16* __restrict__ whi,
                         __nv_bfloat16* __restrict__ wlo) {
    int idx = blockIdx.x * blockDim.x + threadIdx.x;
    if (idx >= 128 * TN) return;
    int k = idx / TN, nn = idx - k * TN;
    float v = W[idx];
    __nv_bfloat16 hi = __float2bfloat16_rn(v);
    __nv_bfloat16 lo = __float2bfloat16_rn(v - __bfloat162float(hi));
    int c = k >> 3;
    int off = nn * 256 + (((c ^ (nn & 7)) << 4) | ((k & 7) << 1));
    *(__nv_bfloat16*)((char*)whi + off) = hi;
    *(__nv_bfloat16*)((char*)wlo + off) = lo;
}

// ---------------- mma.sync GEMM (row range [r0, n)) ----------------
template<int TN, bool RELU, bool SCALE>
__global__ void __launch_bounds__(256)
gemm_mma_k(const float* __restrict__ X, float* __restrict__ out, int r0, int n,
           const __nv_bfloat16* __restrict__ gwhi, const __nv_bfloat16* __restrict__ gwlo) {
    extern __shared__ char sm[];
    constexpr int NT = TN / 16;
    char* xhi = sm;
    char* xlo = sm + 32768;
    char* whi = sm + 65536;
    char* wlo = whi + TN * 256;

    int tid = threadIdx.x;
    int m0 = r0 + blockIdx.x * 128;

    {
        const uint4* gh = (const uint4*)gwhi;
        const uint4* gl = (const uint4*)gwlo;
        uint4* dh = (uint4*)whi;
        uint4* dl = (uint4*)wlo;
        #pragma unroll 4
        for (int i = tid; i < TN * 16; i += 256) { dh[i] = gh[i]; dl[i] = gl[i]; }
    }
    {
        int r = tid >> 1, h = tid & 1;
        int row = m0 + r;
        bool ok = row < n;
        const float4* xr = (const float4*)(X + (size_t)row * 128) + h * 16;
        const float4 z4 = make_float4(0.f, 0.f, 0.f, 0.f);
        #pragma unroll
        for (int j = 0; j < 8; j++) {
            float4 v0 = ok ? xr[j * 2] : z4;
            float4 v1 = ok ? xr[j * 2 + 1] : z4;
            if (RELU) { relu4(v0); relu4(v1); }
            uint4 hv, lv;
            hv.x = pack2(v0.x, v0.y); hv.y = pack2(v0.z, v0.w);
            hv.z = pack2(v1.x, v1.y); hv.w = pack2(v1.z, v1.w);
            __nv_bfloat162 h0 = *(__nv_bfloat162*)&hv.x;
            __nv_bfloat162 h1 = *(__nv_bfloat162*)&hv.y;
            __nv_bfloat162 h2 = *(__nv_bfloat162*)&hv.z;
            __nv_bfloat162 h3 = *(__nv_bfloat162*)&hv.w;
            lv.x = pack2(v0.x - __low2float(h0), v0.y - __high2float(h0));
            lv.y = pack2(v0.z - __low2float(h1), v0.w - __high2float(h1));
            lv.z = pack2(v1.x - __low2float(h2), v1.y - __high2float(h2));
            lv.w = pack2(v1.z - __low2float(h3), v1.w - __high2float(h3));
            int c = h * 8 + j;
            int off = r * 256 + ((c ^ (r & 7)) << 4);
            *(uint4*)(xhi + off) = hv;
            *(uint4*)(xlo + off) = lv;
        }
    }
    __syncthreads();

    int wrp = tid >> 5, lane = tid & 31;
    int wm = wrp & 3;
    int wnb = (wrp >> 2) * (TN / 2);
    uint32_t xhi_u = smem_u32(xhi), xlo_u = smem_u32(xlo);
    uint32_t whi_u = smem_u32(whi), wlo_u = smem_u32(wlo);
    int a_row_in = ((lane >> 3) & 1) * 8 + (lane & 7);
    int a_kc = lane >> 4;
    int b_row_in = ((lane >> 4) << 3) + (lane & 7);
    int b_kc = (lane >> 3) & 1;

    float acc[2][NT][4];
    #pragma unroll
    for (int i = 0; i < 2; i++)
        #pragma unroll
        for (int j = 0; j < NT; j++)
            #pragma unroll
            for (int q = 0; q < 4; q++) acc[i][j][q] = 0.f;

    #pragma unroll
    for (int k = 0; k < 8; k++) {
        int c0 = k * 2;
        uint32_t ahi[2][4], alo[2][4];
        #pragma unroll
        for (int mt = 0; mt < 2; mt++) {
            int rr = wm * 32 + mt * 16 + a_row_in;
            int cc = c0 + a_kc;
            uint32_t off = rr * 256 + (((cc ^ (rr & 7)) & 15) << 4);
            ldsm_x4(ahi[mt], xhi_u + off);
            ldsm_x4(alo[mt], xlo_u + off);
        }
        uint32_t bhi[NT][2], blo[NT][2];
        #pragma unroll
        for (int nt = 0; nt < NT; nt += 2) {
            int rr = wnb + nt * 8 + b_row_in;
            int cc = c0 + b_kc;
            uint32_t off = rr * 256 + (((cc ^ (rr & 7)) & 15) << 4);
            uint32_t t[4];
            ldsm_x4(t, whi_u + off);
            bhi[nt][0] = t[0]; bhi[nt][1] = t[1];
            bhi[nt + 1][0] = t[2]; bhi[nt + 1][1] = t[3];
            ldsm_x4(t, wlo_u + off);
            blo[nt][0] = t[0]; blo[nt][1] = t[1];
            blo[nt + 1][0] = t[2]; blo[nt + 1][1] = t[3];
        }
        #pragma unroll
        for (int mt = 0; mt < 2; mt++)
            #pragma unroll
            for (int nt = 0; nt < NT; nt++) {
                mma_bf16(acc[mt][nt], ahi[mt], bhi[nt]);
                mma_bf16(acc[mt][nt], ahi[mt], blo[nt]);
                mma_bf16(acc[mt][nt], alo[mt], bhi[nt]);
            }
    }

    #pragma unroll
    for (int mt = 0; mt < 2; mt++) {
        int row0 = m0 + wm * 32 + mt * 16 + (lane >> 2);
        int row1 = row0 + 8;
        float dv0 = 1.f, dv1 = 1.f;
        if (SCALE) {
            dv0 = (row0 < n) ? g_dinv[row0] : 0.f;
            dv1 = (row1 < n) ? g_dinv[row1] : 0.f;
        }
        #pragma unroll
        for (int nt = 0; nt < NT; nt++) {
            int col = wnb + nt * 8 + (lane & 3) * 2;
            if (row0 < n)
                *(float2*)(out + (size_t)row0 * TN + col) =
                    make_float2(acc[mt][nt][0] * dv0, acc[mt][nt][1] * dv0);
            if (row1 < n)
                *(float2*)(out + (size_t)row1 * TN + col) =
                    make_float2(acc[mt][nt][2] * dv1, acc[mt][nt][3] * dv1);
        }
    }
}

// ---------------- pull aggregation (node range [n0, n1)) ----------------
template<int D, bool SRCSCALE>
__global__ void agg_k(const float* __restrict__ tmp, const float* __restrict__ bias,
                      float* __restrict__ out, int n0, int n1) {
    int w = n0 + ((blockIdx.x * blockDim.x + threadIdx.x) >> 5);
    if (w >= n1) return;
    int l = threadIdx.x & 31;
    int s0 = g_rowptr[w], s1 = g_rowptr[w + 1];
    float dv = g_dinv[w];
    if (D == 128) {
        const float4* t = (const float4*)tmp;
        float4 sv = t[(size_t)w * 32 + l];
        float4 acc;
        if (SRCSCALE) {
            acc.x = sv.x * dv; acc.y = sv.y * dv; acc.z = sv.z * dv; acc.w = sv.w * dv;
        } else acc = sv;
        for (int j = s0; j < s1; j++) {
            int s = g_esrc[j];
            float4 v = t[(size_t)s * 32 + l];
            if (SRCSCALE) {
                float ds = g_dinv[s];
                acc.x = fmaf(v.x, ds, acc.x); acc.y = fmaf(v.y, ds, acc.y);
                acc.z = fmaf(v.z, ds, acc.z); acc.w = fmaf(v.w, ds, acc.w);
            } else {
                acc.x += v.x; acc.y += v.y; acc.z += v.z; acc.w += v.w;
            }
        }
        float4 bb = ((const float4*)bias)[l];
        float4 o;
        o.x = fmaf(acc.x, dv, bb.x); o.y = fmaf(acc.y, dv, bb.y);
        o.z = fmaf(acc.z, dv, bb.z); o.w = fmaf(acc.w, dv, bb.w);
        ((float4*)out)[(size_t)w * 32 + l] = o;
    } else {
        const float2* t = (const float2*)tmp;
        float2 acc = t[(size_t)w * 32 + l];
        for (int j = s0; j < s1; j++) {
            float2 v = t[(size_t)g_esrc[j] * 32 + l];
            acc.x += v.x; acc.y += v.y;
        }
        float2 bb = ((const float2*)bias)[l];
        ((float2*)out)[(size_t)w * 32 + l] =
            make_float2(fmaf(acc.x, dv, bb.x), fmaf(acc.y, dv, bb.y));
    }
}

// ---------------- decode: 2 pairs per warp, float4 loads ----------------
__global__ void decode_k(const float* __restrict__ z, const void* eli,
                         float* __restrict__ out, int EL) {
    int gid = blockIdx.x * blockDim.x + threadIdx.x;
    int lane = threadIdx.x & 31;
    int p = (gid >> 5) * 2 + (lane >> 4);
    if (p >= EL) return;
    int l = lane & 15;
    int is64 = g_is64;
    int a = eidx(eli, (size_t)p, is64);
    int b = eidx(eli, (size_t)EL + p, is64);
    const float4* z4 = (const float4*)z;
    float4 va = z4[(size_t)a * 16 + l];
    float4 vb = z4[(size_t)b * 16 + l];
    float s = va.x * vb.x + va.y * vb.y + va.z * vb.z + va.w * vb.w;
    #pragma unroll
    for (int off = 8; off > 0; off >>= 1)
        s += __shfl_xor_sync(0xffffffffu, s, off);
    if (l == 0) out[p] = s;
}

// ---------------- launch (R8 schedule: fork preproc; half-split ladder) ------
extern "C" void kernel_launch(void* const* d_in, const int* in_sizes, int n_in,
                              void* d_out, int out_size) {
    const float* x  = (const float*)d_in[0];
    const void*  ei = d_in[1];
    const void*  eli= d_in[2];
    const float* W1 = (const float*)d_in[3];
    const float* b1 = (const float*)d_in[4];
    const float* W2 = (const float*)d_in[5];
    const float* b2 = (const float*)d_in[6];
    const float* W3 = (const float*)d_in[7];
    const float* b3 = (const float*)d_in[8];
    float* out = (float*)d_out;

    int N  = in_sizes[0] / 128;
    int E  = in_sizes[1] / 2;
    int EL = in_sizes[2] / 2;

    float *A, *B;
    cudaGetSymbolAddress((void**)&A, g_bufA);
    cudaGetSymbolAddress((void**)&B, g_bufB);
    __nv_bfloat16* wbase;
    cudaGetSymbolAddress((void**)&wbase, g_w);
    __nv_bfloat16* w1h = wbase;             __nv_bfloat16* w1l = wbase + 1 * 16384;
    __nv_bfloat16* w2h = wbase + 2 * 16384; __nv_bfloat16* w2l = wbase + 3 * 16384;
    __nv_bfloat16* w3h = wbase + 4 * 16384; __nv_bfloat16* w3l = wbase + 5 * 16384;

    static cudaStream_t s2 = nullptr;
    static cudaEvent_t evF, evJ, evG1, evG2a, evG2b, evG3a, evG3b, evA3b;
    if (!s2) {
        cudaStreamCreateWithFlags(&s2, cudaStreamNonBlocking);
        cudaEventCreateWithFlags(&evF,  cudaEventDisableTiming);
        cudaEventCreateWithFlags(&evJ,  cudaEventDisableTiming);
        cudaEventCreateWithFlags(&evG1, cudaEventDisableTiming);
        cudaEventCreateWithFlags(&evG2a, cudaEventDisableTiming);
        cudaEventCreateWithFlags(&evG2b, cudaEventDisableTiming);
        cudaEventCreateWithFlags(&evG3a, cudaEventDisableTiming);
        cudaEventCreateWithFlags(&evG3b, cudaEventDisableTiming);
        cudaEventCreateWithFlags(&evA3b, cudaEventDisableTiming);
    }

    int smem128 = 65536 + 2 * 128 * 256;
    int smem64  = 65536 + 2 * 64 * 256;
    cudaFuncSetAttribute(gemm_mma_k<128, false, false>, cudaFuncAttributeMaxDynamicSharedMemorySize, smem128);
    cudaFuncSetAttribute(gemm_mma_k<128, true,  true>,  cudaFuncAttributeMaxDynamicSharedMemorySize, smem128);
    cudaFuncSetAttribute(gemm_mma_k<64,  true,  true>,  cudaFuncAttributeMaxDynamicSharedMemorySize, smem64);

    int nb = (N + 511) / 512;
    int h  = (N / 2 + 127) & ~127;
    int gg0 = (h + 127) / 128;
    int gg1 = (N - h + 127) / 128;
    int ab0 = (h * 32 + 255) / 256;
    int ab1 = ((N - h) * 32 + 255) / 256;

    // fork: preprocessing on s2
    cudaEventRecord(evF, 0);
    cudaStreamWaitEvent(s2, evF, 0);
    init_k<<<(N + 255) / 256, 256, 0, s2>>>(ei, N);
    count_k<<<(E + 255) / 256, 256, 0, s2>>>(ei, E);
    scan1_k<<<nb, 512, 0, s2>>>(N);
    scan2_k<<<1, 512, 0, s2>>>(nb);
    scan3_k<<<nb, 512, 0, s2>>>(N, E);
    fill_k<<<(E + 255) / 256, 256, 0, s2>>>(ei, E);
    cudaEventRecord(evJ, s2);

    // s0: weight splits + full layer-1 GEMM (independent of preprocessing)
    wsplit_k<128><<<(128 * 128 + 255) / 256, 256>>>(W1, w1h, w1l);
    wsplit_k<128><<<(128 * 128 + 255) / 256, 256>>>(W2, w2h, w2l);
    wsplit_k<64><<<(128 * 64 + 255) / 256, 256>>>(W3, w3h, w3l);
    gemm_mma_k<128, false, false><<<(N + 127) / 128, 256, smem128>>>(x, A, 0, N, w1h, w1l);
    cudaEventRecord(evG1, 0);

    // pipeline: half0 on s0, half1 on s2 (R8 ladder)
    cudaStreamWaitEvent(0, evJ, 0);
    agg_k<128, true><<<ab0, 256>>>(A, b1, B, 0, h);
    gemm_mma_k<128, true, true><<<gg0, 256, smem128>>>(B, A, 0, h, w2h, w2l);
    cudaEventRecord(evG2a, 0);

    cudaStreamWaitEvent(s2, evG1, 0);
    agg_k<128, true><<<ab1, 256, 0, s2>>>(A, b1, B, h, N);
    gemm_mma_k<128, true, true><<<gg1, 256, smem128, s2>>>(B, A, h, N, w2h, w2l);
    cudaEventRecord(evG2b, s2);

    cudaStreamWaitEvent(0, evG2b, 0);
    agg_k<128, false><<<ab0, 256>>>(A, b2, B, 0, h);
    gemm_mma_k<64, true, true><<<gg0, 256, smem64>>>(B, A, 0, h, w3h, w3l);
    cudaEventRecord(evG3a, 0);

    cudaStreamWaitEvent(s2, evG2a, 0);
    agg_k<128, false><<<ab1, 256, 0, s2>>>(A, b2, B, h, N);
    gemm_mma_k<64, true, true><<<gg1, 256, smem64, s2>>>(B, A, h, N, w3h, w3l);
    cudaEventRecord(evG3b, s2);

    cudaStreamWaitEvent(0, evG3b, 0);
    agg_k<64, false><<<ab0, 256>>>(A, b3, B, 0, h);

    cudaStreamWaitEvent(s2, evG3a, 0);
    agg_k<64, false><<<ab1, 256, 0, s2>>>(A, b3, B, h, N);
    cudaEventRecord(evA3b, s2);

    cudaStreamWaitEvent(0, evA3b, 0);
    decode_k<<<((EL + 1) / 2 * 32 + 255) / 256, 256>>>(B, eli, out, EL);
}